// round 1
// baseline (speedup 1.0000x reference)
#include <cuda_runtime.h>
#include <cfloat>
#include <cstddef>

#define NN 4096
#define CC 256
#define VV 4

// ---------------- scratch (static device globals; no cudaMalloc) ----------------
__device__ float g_dn[NN * VV * CC];          // normalized desc [n][v][c]
__device__ float g_recon[VV * NN * CC];       // dn_v @ W_rec, per view
__device__ float g_relWT[12 * CC];            // rel @ W_T per ordered pair
__device__ float g_sim[(size_t)NN * NN];      // similarity matrix (one pair at a time)
__device__ float g_p[(size_t)NN * NN];        // exp'd (unnormalized) softmax numerators
__device__ int   g_rowidx[NN];
__device__ float g_rowsum[NN];
__device__ int   g_colidx[NN];
__device__ float g_colsum[NN];
__device__ float g_colmax[NN];
__device__ float g_colmax_part[32 * NN];
__device__ int   g_colidx_part[32 * NN];
__device__ float g_colsum_part[32 * NN];
__device__ float g_soft_row[NN * CC];
__device__ float g_soft_col[NN * CC];
__device__ float g_sq_part[12 * 32];
__device__ int   g_cnt_part[12 * 32];

__constant__ int c_OPI[12] = {0,0,0,1,1,1,2,2,2,3,3,3};
__constant__ int c_OPJ[12] = {1,2,3,0,2,3,0,1,3,0,1,2};

// ---------------- fast exp (FMA-pipe polynomial, avoids MUFU throughput wall) ----
__device__ __forceinline__ float fast_exp(float x) {
    // x in [-2, 0] here (sim - max, sim in [-1,1]).
    float y = x * 1.4426950408889634f;       // log2(e)
    float n = rintf(y);
    float f = y - n;                         // f in [-0.5, 0.5]
    // 2^f via Taylor in ln2*f, degree 6: rel err ~1.2e-7
    const float c1 = 0.6931471805599453f;
    const float c2 = 0.2402265069591007f;
    const float c3 = 0.0555041086648216f;
    const float c4 = 0.0096181291076285f;
    const float c5 = 0.0013333558146428f;
    const float c6 = 0.0001540353039338f;
    float r = c6;
    r = r * f + c5;
    r = r * f + c4;
    r = r * f + c3;
    r = r * f + c2;
    r = r * f + c1;
    r = r * f + 1.0f;
    int e = (int)n;
    return __int_as_float(__float_as_int(r) + (e << 23));
}

// ---------------- normalize: one block per (n,v) row of 256 ----------------------
__global__ void __launch_bounds__(256) normalize_kernel(const float* __restrict__ desc) {
    int rv = blockIdx.x;
    int tid = threadIdx.x;
    __shared__ float ss[256];
    float x = desc[(size_t)rv * CC + tid];
    ss[tid] = x * x;
    __syncthreads();
    for (int off = 128; off > 0; off >>= 1) {
        if (tid < off) ss[tid] += ss[tid + off];
        __syncthreads();
    }
    float den = fmaxf(sqrtf(ss[0]), 1e-12f);
    g_dn[(size_t)rv * CC + tid] = x / den;
}

// ---------------- relWT[op][c] = concat(T[i],T[j]) @ W_T -------------------------
__global__ void __launch_bounds__(256) relwt_kernel(const float* __restrict__ T,
                                                    const float* __restrict__ WT) {
    int op = blockIdx.x;
    int c = threadIdx.x;
    int i = c_OPI[op], j = c_OPJ[op];
    float s = 0.0f;
    #pragma unroll
    for (int k = 0; k < 16; k++) s += T[i * 16 + k] * WT[k * CC + c];
    #pragma unroll
    for (int k = 0; k < 16; k++) s += T[j * 16 + k] * WT[(16 + k) * CC + c];
    g_relWT[op * CC + c] = s;
}

// ---------------- SGEMM C = A @ B^T (sim). 128x128 tile, 8x8 microtile ----------
__global__ void __launch_bounds__(256) gemm_nt_kernel(
    const float* __restrict__ A, int lda,
    const float* __restrict__ B, int ldb,
    float* __restrict__ C, int ldc, int K)
{
    __shared__ float As[8][132];
    __shared__ float Bs[8][132];
    const int tid = threadIdx.x;
    const int lr = tid >> 1;
    const int lk = (tid & 1) * 4;
    const int row0 = blockIdx.y * 128;
    const int col0 = blockIdx.x * 128;
    const float* Ag = A + (size_t)(row0 + lr) * lda + lk;
    const float* Bg = B + (size_t)(col0 + lr) * ldb + lk;
    const int tx = (tid & 15) * 8;
    const int ty = (tid >> 4) * 8;
    float acc[8][8];
    #pragma unroll
    for (int i = 0; i < 8; i++)
        #pragma unroll
        for (int j = 0; j < 8; j++) acc[i][j] = 0.0f;

    for (int k0 = 0; k0 < K; k0 += 8) {
        float4 a = *(const float4*)(Ag + k0);
        float4 b = *(const float4*)(Bg + k0);
        __syncthreads();
        As[lk + 0][lr] = a.x; As[lk + 1][lr] = a.y; As[lk + 2][lr] = a.z; As[lk + 3][lr] = a.w;
        Bs[lk + 0][lr] = b.x; Bs[lk + 1][lr] = b.y; Bs[lk + 2][lr] = b.z; Bs[lk + 3][lr] = b.w;
        __syncthreads();
        #pragma unroll
        for (int kk = 0; kk < 8; kk++) {
            float ar[8], br[8];
            *(float4*)(ar)     = *(const float4*)&As[kk][ty];
            *(float4*)(ar + 4) = *(const float4*)&As[kk][ty + 4];
            *(float4*)(br)     = *(const float4*)&Bs[kk][tx];
            *(float4*)(br + 4) = *(const float4*)&Bs[kk][tx + 4];
            #pragma unroll
            for (int i = 0; i < 8; i++)
                #pragma unroll
                for (int j = 0; j < 8; j++)
                    acc[i][j] += ar[i] * br[j];
        }
    }
    #pragma unroll
    for (int i = 0; i < 8; i++) {
        float* Cp = C + (size_t)(row0 + ty + i) * ldc + col0 + tx;
        *(float4*)(Cp)     = make_float4(acc[i][0], acc[i][1], acc[i][2], acc[i][3]);
        *(float4*)(Cp + 4) = make_float4(acc[i][4], acc[i][5], acc[i][6], acc[i][7]);
    }
}

// ---------------- SGEMM C = A @ B or A^T @ B, N-dim=64 tiles, 8x4 microtile ------
// ATRANS=false: A is M x K (lda = row stride). ATRANS=true: A is K x M.
// B is K x N (ldb). Optional per-output-row denominator (softmax normalization).
template <bool ATRANS>
__global__ void __launch_bounds__(256) gemm_ab_kernel(
    const float* __restrict__ A, int lda,
    const float* __restrict__ B, int ldb,
    float* __restrict__ C, int ldc, int K,
    const float* __restrict__ den)
{
    __shared__ float As[8][132];
    __shared__ float Bs[8][68];
    const int tid = threadIdx.x;
    const int m0 = blockIdx.y * 128;
    const int n0 = blockIdx.x * 64;
    const int tx = (tid & 15) * 4;
    const int ty = (tid >> 4) * 8;
    const int lr = tid >> 1;          // NN path
    const int lk = (tid & 1) * 4;
    const int ak = tid >> 5;          // TN path
    const int am = (tid & 31) * 4;
    const bool bload = tid < 128;
    const int bk = tid >> 4;
    const int bc = (tid & 15) * 4;

    float acc[8][4];
    #pragma unroll
    for (int i = 0; i < 8; i++)
        #pragma unroll
        for (int j = 0; j < 4; j++) acc[i][j] = 0.0f;

    for (int k0 = 0; k0 < K; k0 += 8) {
        float4 a, b;
        if (!ATRANS) {
            a = *(const float4*)(A + (size_t)(m0 + lr) * lda + k0 + lk);
        } else {
            a = *(const float4*)(A + (size_t)(k0 + ak) * lda + m0 + am);
        }
        if (bload) b = *(const float4*)(B + (size_t)(k0 + bk) * ldb + n0 + bc);
        __syncthreads();
        if (!ATRANS) {
            As[lk + 0][lr] = a.x; As[lk + 1][lr] = a.y; As[lk + 2][lr] = a.z; As[lk + 3][lr] = a.w;
        } else {
            *(float4*)&As[ak][am] = a;
        }
        if (bload) *(float4*)&Bs[bk][bc] = b;
        __syncthreads();
        #pragma unroll
        for (int kk = 0; kk < 8; kk++) {
            float ar[8], br[4];
            *(float4*)(ar)     = *(const float4*)&As[kk][ty];
            *(float4*)(ar + 4) = *(const float4*)&As[kk][ty + 4];
            *(float4*)(br)     = *(const float4*)&Bs[kk][tx];
            #pragma unroll
            for (int i = 0; i < 8; i++)
                #pragma unroll
                for (int j = 0; j < 4; j++)
                    acc[i][j] += ar[i] * br[j];
        }
    }
    #pragma unroll
    for (int i = 0; i < 8; i++) {
        int row = m0 + ty + i;
        float s = den ? (1.0f / den[row]) : 1.0f;
        float* Cp = C + (size_t)row * ldc + n0 + tx;
        *(float4*)Cp = make_float4(acc[i][0] * s, acc[i][1] * s, acc[i][2] * s, acc[i][3] * s);
    }
}

// ---------------- row stats + exp write: one block per row ----------------------
__global__ void __launch_bounds__(256) rowstats_kernel() {
    int row = blockIdx.x;
    int tid = threadIdx.x;
    const float* srow = g_sim + (size_t)row * NN;
    float v[16];
    float bmax = -FLT_MAX;
    int bidx = 0;
    #pragma unroll
    for (int s = 0; s < 16; s++) {
        int idx = tid + 256 * s;
        v[s] = srow[idx];
        if (v[s] > bmax) { bmax = v[s]; bidx = idx; }   // first occurrence within thread
    }
    __shared__ float sv[256];
    __shared__ int si[256];
    sv[tid] = bmax; si[tid] = bidx;
    __syncthreads();
    for (int off = 128; off > 0; off >>= 1) {
        if (tid < off) {
            float v2 = sv[tid + off]; int i2 = si[tid + off];
            if (v2 > sv[tid] || (v2 == sv[tid] && i2 < si[tid])) { sv[tid] = v2; si[tid] = i2; }
        }
        __syncthreads();
    }
    float rmax = sv[0];
    int ridx = si[0];
    __syncthreads();
    float lsum = 0.0f;
    float* prow = g_p + (size_t)row * NN;
    #pragma unroll
    for (int s = 0; s < 16; s++) {
        float e = fast_exp(v[s] - rmax);
        prow[tid + 256 * s] = e;
        lsum += e;
    }
    sv[tid] = lsum;
    __syncthreads();
    for (int off = 128; off > 0; off >>= 1) {
        if (tid < off) sv[tid] += sv[tid + off];
        __syncthreads();
    }
    if (tid == 0) { g_rowidx[row] = ridx; g_rowsum[row] = sv[0]; }
}

// ---------------- column stats (partials -> deterministic reduce) ---------------
__global__ void __launch_bounds__(256) colmax_part_kernel() {  // grid (16, 32)
    int m = blockIdx.x * 256 + threadIdx.x;
    int n0 = blockIdx.y * 128;
    float bmax = -FLT_MAX;
    int bidx = 0;
    for (int r = 0; r < 128; r++) {
        float vv = g_sim[(size_t)(n0 + r) * NN + m];
        if (vv > bmax) { bmax = vv; bidx = n0 + r; }
    }
    g_colmax_part[blockIdx.y * NN + m] = bmax;
    g_colidx_part[blockIdx.y * NN + m] = bidx;
}

__global__ void __launch_bounds__(256) colmax_reduce_kernel() {  // grid 16
    int m = blockIdx.x * 256 + threadIdx.x;
    float bmax = -FLT_MAX;
    int bidx = 0;
    for (int s = 0; s < 32; s++) {                 // ascending n-segments: first occurrence kept
        float vv = g_colmax_part[s * NN + m];
        if (vv > bmax) { bmax = vv; bidx = g_colidx_part[s * NN + m]; }
    }
    g_colmax[m] = bmax;
    g_colidx[m] = bidx;
}

__global__ void __launch_bounds__(256) colexp_kernel() {  // grid (16, 32)
    int m = blockIdx.x * 256 + threadIdx.x;
    int n0 = blockIdx.y * 128;
    float cmax = g_colmax[m];
    float lsum = 0.0f;
    for (int r = 0; r < 128; r++) {
        size_t off = (size_t)(n0 + r) * NN + m;
        float e = fast_exp(g_sim[off] - cmax);
        g_p[off] = e;
        lsum += e;
    }
    g_colsum_part[blockIdx.y * NN + m] = lsum;
}

__global__ void __launch_bounds__(256) colsum_reduce_kernel() {  // grid 16
    int m = blockIdx.x * 256 + threadIdx.x;
    float s = 0.0f;
    for (int k = 0; k < 32; k++) s += g_colsum_part[k * NN + m];
    g_colsum[m] = s;
}

// ---------------- per-ordered-pair loss partials ---------------------------------
__global__ void __launch_bounds__(256) loss_kernel(
    const int* __restrict__ idxA, const int* __restrict__ idxB,
    const float* __restrict__ soft, const float* __restrict__ recon, int op)
{
    int tid = threadIdx.x;
    int b = blockIdx.x;   // 32 blocks, 128 rows each
    const float* relw = g_relWT + op * CC;
    float relc = relw[tid];
    float lsum = 0.0f;
    int lcnt = 0;
    for (int r = 0; r < 128; r++) {
        int row = b * 128 + r;
        int a = idxA[row];
        if (idxB[a] == row) {
            float d = recon[(size_t)row * CC + tid] + relc - soft[(size_t)row * CC + tid];
            lsum += d * d;
            if (tid == 0) lcnt++;
        }
    }
    __shared__ float ss[256];
    ss[tid] = lsum;
    __syncthreads();
    for (int off = 128; off > 0; off >>= 1) {
        if (tid < off) ss[tid] += ss[tid + off];
        __syncthreads();
    }
    if (tid == 0) {
        g_sq_part[op * 32 + b] = ss[0];
        g_cnt_part[op * 32 + b] = lcnt;
    }
}

__global__ void finalize_kernel(float* __restrict__ out) {
    if (threadIdx.x == 0) {
        float total = 0.0f, count = 0.0f;
        for (int op = 0; op < 12; op++) {
            float sq = 0.0f;
            int cnt = 0;
            for (int b = 0; b < 32; b++) {
                sq += g_sq_part[op * 32 + b];
                cnt += g_cnt_part[op * 32 + b];
            }
            if (cnt > 0) {
                total += sq / fmaxf((float)cnt * (float)CC, 1.0f);
                count += 1.0f;
            }
        }
        out[0] = (count > 0.0f) ? (total / fmaxf(count, 1.0f)) : 0.0f;
    }
}

// ---------------- host launch ----------------------------------------------------
extern "C" void kernel_launch(void* const* d_in, const int* in_sizes, int n_in,
                              void* d_out, int out_size)
{
    const float* desc  = (const float*)d_in[0];
    const float* sf    = (const float*)d_in[1];
    const float* T     = (const float*)d_in[2];
    const float* W_rec = (const float*)d_in[3];
    const float* W_T   = (const float*)d_in[4];
    float* out = (float*)d_out;

    float *dn, *recon, *sim, *p, *rowsum, *colsum, *soft_row, *soft_col;
    int *rowidx, *colidx;
    cudaGetSymbolAddress((void**)&dn, g_dn);
    cudaGetSymbolAddress((void**)&recon, g_recon);
    cudaGetSymbolAddress((void**)&sim, g_sim);
    cudaGetSymbolAddress((void**)&p, g_p);
    cudaGetSymbolAddress((void**)&rowsum, g_rowsum);
    cudaGetSymbolAddress((void**)&colsum, g_colsum);
    cudaGetSymbolAddress((void**)&soft_row, g_soft_row);
    cudaGetSymbolAddress((void**)&soft_col, g_soft_col);
    cudaGetSymbolAddress((void**)&rowidx, g_rowidx);
    cudaGetSymbolAddress((void**)&colidx, g_colidx);

    // 1. normalize
    normalize_kernel<<<NN * VV, 256>>>(desc);

    // 2. rel @ W_T for all 12 ordered pairs
    relwt_kernel<<<12, 256>>>(T, W_T);

    // 3. recon[v] = dn_v @ W_rec
    for (int v = 0; v < VV; v++) {
        gemm_ab_kernel<false><<<dim3(CC / 64, NN / 128), 256>>>(
            dn + v * CC, VV * CC, W_rec, CC,
            recon + (size_t)v * NN * CC, CC, CC, nullptr);
    }

    auto OP = [](int i, int j) { return i * 3 + (j < i ? j : j - 1); };

    // 4. pairs
    for (int i = 0; i < VV; i++) {
        for (int j = i + 1; j < VV; j++) {
            // sim = dn_i @ dn_j^T
            gemm_nt_kernel<<<dim3(NN / 128, NN / 128), 256>>>(
                dn + i * CC, VV * CC, dn + j * CC, VV * CC, sim, NN, CC);

            // row direction (ordered pair (i,j))
            rowstats_kernel<<<NN, 256>>>();
            gemm_ab_kernel<false><<<dim3(CC / 64, NN / 128), 256>>>(
                p, NN, sf + j * CC, VV * CC, soft_row, CC, NN, rowsum);

            // column direction (ordered pair (j,i)) — uses sim^T implicitly
            colmax_part_kernel<<<dim3(NN / 256, 32), 256>>>();
            colmax_reduce_kernel<<<NN / 256, 256>>>();
            colexp_kernel<<<dim3(NN / 256, 32), 256>>>();
            colsum_reduce_kernel<<<NN / 256, 256>>>();
            gemm_ab_kernel<true><<<dim3(CC / 64, NN / 128), 256>>>(
                p, NN, sf + i * CC, VV * CC, soft_col, CC, NN, colsum);

            // losses for both ordered directions
            loss_kernel<<<32, 256>>>(rowidx, colidx, soft_row,
                                     recon + (size_t)i * NN * CC, OP(i, j));
            loss_kernel<<<32, 256>>>(colidx, rowidx, soft_col,
                                     recon + (size_t)j * NN * CC, OP(j, i));
        }
    }

    // 5. finalize
    finalize_kernel<<<1, 32>>>(out);
}

// round 2
// speedup vs baseline: 1.6646x; 1.6646x over previous
#include <cuda_runtime.h>
#include <cfloat>
#include <cstddef>

#define NN 4096
#define CC 256
#define VV 4
#define SPLITK 8
#define KCHUNK (NN / SPLITK)

// ---------------- scratch (static device globals; no cudaMalloc) ----------------
__device__ float g_dn[NN * VV * CC];          // normalized desc [n][v][c]
__device__ float g_recon[VV * NN * CC];       // dn_v @ W_rec, per view
__device__ float g_relWT[12 * CC];            // rel @ W_T per ordered pair
__device__ float g_sim[(size_t)NN * NN];      // similarity matrix (one pair at a time)
__device__ float g_p[(size_t)NN * NN];        // exp'd (unnormalized) softmax numerators
__device__ float g_cpart[(size_t)SPLITK * NN * CC];  // split-K partials
__device__ int   g_rowidx[NN];
__device__ float g_rowsum[NN];
__device__ int   g_colidx[NN];
__device__ float g_colsum[NN];
__device__ float g_colmax[NN];
__device__ float g_colmax_part[32 * NN];
__device__ int   g_colidx_part[32 * NN];
__device__ float g_colsum_part[32 * NN];
__device__ float g_soft_row[NN * CC];
__device__ float g_soft_col[NN * CC];
__device__ float g_sq_part[12 * 32];
__device__ int   g_cnt_part[12 * 32];

__constant__ int c_OPI[12] = {0,0,0,1,1,1,2,2,2,3,3,3};
__constant__ int c_OPJ[12] = {1,2,3,0,2,3,0,1,3,0,1,2};

// ---------------- fast exp (FMA-pipe polynomial, avoids MUFU throughput wall) ----
__device__ __forceinline__ float fast_exp(float x) {
    float y = x * 1.4426950408889634f;       // log2(e)
    float n = rintf(y);
    float f = y - n;                         // f in [-0.5, 0.5]
    const float c1 = 0.6931471805599453f;
    const float c2 = 0.2402265069591007f;
    const float c3 = 0.0555041086648216f;
    const float c4 = 0.0096181291076285f;
    const float c5 = 0.0013333558146428f;
    const float c6 = 0.0001540353039338f;
    float r = c6;
    r = r * f + c5;
    r = r * f + c4;
    r = r * f + c3;
    r = r * f + c2;
    r = r * f + c1;
    r = r * f + 1.0f;
    int e = (int)n;
    return __int_as_float(__float_as_int(r) + (e << 23));
}

// ---------------- normalize: one block per (n,v) row of 256 ----------------------
__global__ void __launch_bounds__(256) normalize_kernel(const float* __restrict__ desc) {
    int rv = blockIdx.x;
    int tid = threadIdx.x;
    __shared__ float ss[256];
    float x = desc[(size_t)rv * CC + tid];
    ss[tid] = x * x;
    __syncthreads();
    for (int off = 128; off > 0; off >>= 1) {
        if (tid < off) ss[tid] += ss[tid + off];
        __syncthreads();
    }
    float den = fmaxf(sqrtf(ss[0]), 1e-12f);
    g_dn[(size_t)rv * CC + tid] = x / den;
}

// ---------------- relWT[op][c] = concat(T[i],T[j]) @ W_T -------------------------
__global__ void __launch_bounds__(256) relwt_kernel(const float* __restrict__ T,
                                                    const float* __restrict__ WT) {
    int op = blockIdx.x;
    int c = threadIdx.x;
    int i = c_OPI[op], j = c_OPJ[op];
    float s = 0.0f;
    #pragma unroll
    for (int k = 0; k < 16; k++) s += T[i * 16 + k] * WT[k * CC + c];
    #pragma unroll
    for (int k = 0; k < 16; k++) s += T[j * 16 + k] * WT[(16 + k) * CC + c];
    g_relWT[op * CC + c] = s;
}

// ---------------- SGEMM C = A @ B^T (sim). 128x128 tile, 8x8 microtile ----------
__global__ void __launch_bounds__(256) gemm_nt_kernel(
    const float* __restrict__ A, int lda,
    const float* __restrict__ B, int ldb,
    float* __restrict__ C, int ldc, int K)
{
    __shared__ float As[8][132];
    __shared__ float Bs[8][132];
    const int tid = threadIdx.x;
    const int lr = tid >> 1;
    const int lk = (tid & 1) * 4;
    const int row0 = blockIdx.y * 128;
    const int col0 = blockIdx.x * 128;
    const float* Ag = A + (size_t)(row0 + lr) * lda + lk;
    const float* Bg = B + (size_t)(col0 + lr) * ldb + lk;
    const int tx = (tid & 15) * 8;
    const int ty = (tid >> 4) * 8;
    float acc[8][8];
    #pragma unroll
    for (int i = 0; i < 8; i++)
        #pragma unroll
        for (int j = 0; j < 8; j++) acc[i][j] = 0.0f;

    for (int k0 = 0; k0 < K; k0 += 8) {
        float4 a = *(const float4*)(Ag + k0);
        float4 b = *(const float4*)(Bg + k0);
        __syncthreads();
        As[lk + 0][lr] = a.x; As[lk + 1][lr] = a.y; As[lk + 2][lr] = a.z; As[lk + 3][lr] = a.w;
        Bs[lk + 0][lr] = b.x; Bs[lk + 1][lr] = b.y; Bs[lk + 2][lr] = b.z; Bs[lk + 3][lr] = b.w;
        __syncthreads();
        #pragma unroll
        for (int kk = 0; kk < 8; kk++) {
            float ar[8], br[8];
            *(float4*)(ar)     = *(const float4*)&As[kk][ty];
            *(float4*)(ar + 4) = *(const float4*)&As[kk][ty + 4];
            *(float4*)(br)     = *(const float4*)&Bs[kk][tx];
            *(float4*)(br + 4) = *(const float4*)&Bs[kk][tx + 4];
            #pragma unroll
            for (int i = 0; i < 8; i++)
                #pragma unroll
                for (int j = 0; j < 8; j++)
                    acc[i][j] += ar[i] * br[j];
        }
    }
    #pragma unroll
    for (int i = 0; i < 8; i++) {
        float* Cp = C + (size_t)(row0 + ty + i) * ldc + col0 + tx;
        *(float4*)(Cp)     = make_float4(acc[i][0], acc[i][1], acc[i][2], acc[i][3]);
        *(float4*)(Cp + 4) = make_float4(acc[i][4], acc[i][5], acc[i][6], acc[i][7]);
    }
}

// ---------------- split-K SGEMM: Cpart[z] = A[:, zK:(z+1)K] @ B[zK:(z+1)K, :] ----
// ATRANS=false: A is M x Ktot (lda). ATRANS=true: A is Ktot x M (lda).
// B is Ktot x N (ldb). Output tile 128x64 per CTA, 8x4 microtile.
template <bool ATRANS>
__global__ void __launch_bounds__(256) gemm_splitk_kernel(
    const float* __restrict__ A, int lda,
    const float* __restrict__ B, int ldb)
{
    __shared__ float As[8][132];
    __shared__ float Bs[8][68];
    const int tid = threadIdx.x;
    const int m0 = blockIdx.y * 128;
    const int n0 = blockIdx.x * 64;
    const int kb = blockIdx.z * KCHUNK;
    const int tx = (tid & 15) * 4;
    const int ty = (tid >> 4) * 8;
    const int lr = tid >> 1;          // NN path
    const int lk = (tid & 1) * 4;
    const int ak = tid >> 5;          // TN path
    const int am = (tid & 31) * 4;
    const bool bload = tid < 128;
    const int bk = tid >> 4;
    const int bc = (tid & 15) * 4;

    float acc[8][4];
    #pragma unroll
    for (int i = 0; i < 8; i++)
        #pragma unroll
        for (int j = 0; j < 4; j++) acc[i][j] = 0.0f;

    for (int k0 = kb; k0 < kb + KCHUNK; k0 += 8) {
        float4 a, b;
        if (!ATRANS) {
            a = *(const float4*)(A + (size_t)(m0 + lr) * lda + k0 + lk);
        } else {
            a = *(const float4*)(A + (size_t)(k0 + ak) * lda + m0 + am);
        }
        if (bload) b = *(const float4*)(B + (size_t)(k0 + bk) * ldb + n0 + bc);
        __syncthreads();
        if (!ATRANS) {
            As[lk + 0][lr] = a.x; As[lk + 1][lr] = a.y; As[lk + 2][lr] = a.z; As[lk + 3][lr] = a.w;
        } else {
            *(float4*)&As[ak][am] = a;
        }
        if (bload) *(float4*)&Bs[bk][bc] = b;
        __syncthreads();
        #pragma unroll
        for (int kk = 0; kk < 8; kk++) {
            float ar[8], br[4];
            *(float4*)(ar)     = *(const float4*)&As[kk][ty];
            *(float4*)(ar + 4) = *(const float4*)&As[kk][ty + 4];
            *(float4*)(br)     = *(const float4*)&Bs[kk][tx];
            #pragma unroll
            for (int i = 0; i < 8; i++)
                #pragma unroll
                for (int j = 0; j < 4; j++)
                    acc[i][j] += ar[i] * br[j];
        }
    }
    float* Cp0 = g_cpart + (size_t)blockIdx.z * NN * CC;
    #pragma unroll
    for (int i = 0; i < 8; i++) {
        int row = m0 + ty + i;
        float* Cp = Cp0 + (size_t)row * CC + n0 + tx;
        *(float4*)Cp = make_float4(acc[i][0], acc[i][1], acc[i][2], acc[i][3]);
    }
}

// ---------------- split-K reduce + softmax denominator --------------------------
__global__ void __launch_bounds__(256) splitk_reduce_kernel(
    float* __restrict__ C, const float* __restrict__ den)
{
    int idx = blockIdx.x * 256 + threadIdx.x;   // over NN*CC
    int row = idx >> 8;                          // CC = 256
    float s = 0.0f;
    #pragma unroll
    for (int z = 0; z < SPLITK; z++) s += g_cpart[(size_t)z * NN * CC + idx];
    C[idx] = s / den[row];
}

// ---------------- recon GEMM: z-batched over views, C = dn_v @ W_rec ------------
__global__ void __launch_bounds__(256) recon_gemm_kernel(const float* __restrict__ Wrec) {
    __shared__ float As[8][132];
    __shared__ float Bs[8][68];
    const int tid = threadIdx.x;
    const int v = blockIdx.z;
    const float* A = g_dn + v * CC;              // lda = VV*CC
    float* C = g_recon + (size_t)v * NN * CC;
    const int m0 = blockIdx.y * 128;
    const int n0 = blockIdx.x * 64;
    const int tx = (tid & 15) * 4;
    const int ty = (tid >> 4) * 8;
    const int lr = tid >> 1;
    const int lk = (tid & 1) * 4;
    const bool bload = tid < 128;
    const int bk = tid >> 4;
    const int bc = (tid & 15) * 4;

    float acc[8][4];
    #pragma unroll
    for (int i = 0; i < 8; i++)
        #pragma unroll
        for (int j = 0; j < 4; j++) acc[i][j] = 0.0f;

    for (int k0 = 0; k0 < CC; k0 += 8) {
        float4 a = *(const float4*)(A + (size_t)(m0 + lr) * (VV * CC) + k0 + lk);
        float4 b;
        if (bload) b = *(const float4*)(Wrec + (size_t)(k0 + bk) * CC + n0 + bc);
        __syncthreads();
        As[lk + 0][lr] = a.x; As[lk + 1][lr] = a.y; As[lk + 2][lr] = a.z; As[lk + 3][lr] = a.w;
        if (bload) *(float4*)&Bs[bk][bc] = b;
        __syncthreads();
        #pragma unroll
        for (int kk = 0; kk < 8; kk++) {
            float ar[8], br[4];
            *(float4*)(ar)     = *(const float4*)&As[kk][ty];
            *(float4*)(ar + 4) = *(const float4*)&As[kk][ty + 4];
            *(float4*)(br)     = *(const float4*)&Bs[kk][tx];
            #pragma unroll
            for (int i = 0; i < 8; i++)
                #pragma unroll
                for (int j = 0; j < 4; j++)
                    acc[i][j] += ar[i] * br[j];
        }
    }
    #pragma unroll
    for (int i = 0; i < 8; i++) {
        float* Cp = C + (size_t)(m0 + ty + i) * CC + n0 + tx;
        *(float4*)Cp = make_float4(acc[i][0], acc[i][1], acc[i][2], acc[i][3]);
    }
}

// ---------------- row stats + exp write: one block per row ----------------------
__global__ void __launch_bounds__(256) rowstats_kernel() {
    int row = blockIdx.x;
    int tid = threadIdx.x;
    const float* srow = g_sim + (size_t)row * NN;
    float v[16];
    float bmax = -FLT_MAX;
    int bidx = 0;
    #pragma unroll
    for (int s = 0; s < 16; s++) {
        int idx = tid + 256 * s;
        v[s] = srow[idx];
        if (v[s] > bmax) { bmax = v[s]; bidx = idx; }
    }
    __shared__ float sv[256];
    __shared__ int si[256];
    sv[tid] = bmax; si[tid] = bidx;
    __syncthreads();
    for (int off = 128; off > 0; off >>= 1) {
        if (tid < off) {
            float v2 = sv[tid + off]; int i2 = si[tid + off];
            if (v2 > sv[tid] || (v2 == sv[tid] && i2 < si[tid])) { sv[tid] = v2; si[tid] = i2; }
        }
        __syncthreads();
    }
    float rmax = sv[0];
    int ridx = si[0];
    __syncthreads();
    float lsum = 0.0f;
    float* prow = g_p + (size_t)row * NN;
    #pragma unroll
    for (int s = 0; s < 16; s++) {
        float e = fast_exp(v[s] - rmax);
        prow[tid + 256 * s] = e;
        lsum += e;
    }
    sv[tid] = lsum;
    __syncthreads();
    for (int off = 128; off > 0; off >>= 1) {
        if (tid < off) sv[tid] += sv[tid + off];
        __syncthreads();
    }
    if (tid == 0) { g_rowidx[row] = ridx; g_rowsum[row] = sv[0]; }
}

// ---------------- column stats (partials -> deterministic reduce) ---------------
__global__ void __launch_bounds__(256) colmax_part_kernel() {  // grid (16, 32)
    int m = blockIdx.x * 256 + threadIdx.x;
    int n0 = blockIdx.y * 128;
    float bmax = -FLT_MAX;
    int bidx = 0;
    for (int r = 0; r < 128; r++) {
        float vv = g_sim[(size_t)(n0 + r) * NN + m];
        if (vv > bmax) { bmax = vv; bidx = n0 + r; }
    }
    g_colmax_part[blockIdx.y * NN + m] = bmax;
    g_colidx_part[blockIdx.y * NN + m] = bidx;
}

__global__ void __launch_bounds__(256) colmax_reduce_kernel() {  // grid 16
    int m = blockIdx.x * 256 + threadIdx.x;
    float bmax = -FLT_MAX;
    int bidx = 0;
    for (int s = 0; s < 32; s++) {
        float vv = g_colmax_part[s * NN + m];
        if (vv > bmax) { bmax = vv; bidx = g_colidx_part[s * NN + m]; }
    }
    g_colmax[m] = bmax;
    g_colidx[m] = bidx;
}

__global__ void __launch_bounds__(256) colexp_kernel() {  // grid (16, 32)
    int m = blockIdx.x * 256 + threadIdx.x;
    int n0 = blockIdx.y * 128;
    float cmax = g_colmax[m];
    float lsum = 0.0f;
    for (int r = 0; r < 128; r++) {
        size_t off = (size_t)(n0 + r) * NN + m;
        float e = fast_exp(g_sim[off] - cmax);
        g_p[off] = e;
        lsum += e;
    }
    g_colsum_part[blockIdx.y * NN + m] = lsum;
}

__global__ void __launch_bounds__(256) colsum_reduce_kernel() {  // grid 16
    int m = blockIdx.x * 256 + threadIdx.x;
    float s = 0.0f;
    for (int k = 0; k < 32; k++) s += g_colsum_part[k * NN + m];
    g_colsum[m] = s;
}

// ---------------- per-ordered-pair loss partials ---------------------------------
__global__ void __launch_bounds__(256) loss_kernel(
    const int* __restrict__ idxA, const int* __restrict__ idxB,
    const float* __restrict__ soft, const float* __restrict__ recon, int op)
{
    int tid = threadIdx.x;
    int b = blockIdx.x;   // 32 blocks, 128 rows each
    const float* relw = g_relWT + op * CC;
    float relc = relw[tid];
    float lsum = 0.0f;
    int lcnt = 0;
    for (int r = 0; r < 128; r++) {
        int row = b * 128 + r;
        int a = idxA[row];
        if (idxB[a] == row) {
            float d = recon[(size_t)row * CC + tid] + relc - soft[(size_t)row * CC + tid];
            lsum += d * d;
            if (tid == 0) lcnt++;
        }
    }
    __shared__ float ss[256];
    ss[tid] = lsum;
    __syncthreads();
    for (int off = 128; off > 0; off >>= 1) {
        if (tid < off) ss[tid] += ss[tid + off];
        __syncthreads();
    }
    if (tid == 0) {
        g_sq_part[op * 32 + b] = ss[0];
        g_cnt_part[op * 32 + b] = lcnt;
    }
}

__global__ void finalize_kernel(float* __restrict__ out) {
    if (threadIdx.x == 0) {
        float total = 0.0f, count = 0.0f;
        for (int op = 0; op < 12; op++) {
            float sq = 0.0f;
            int cnt = 0;
            for (int b = 0; b < 32; b++) {
                sq += g_sq_part[op * 32 + b];
                cnt += g_cnt_part[op * 32 + b];
            }
            if (cnt > 0) {
                total += sq / fmaxf((float)cnt * (float)CC, 1.0f);
                count += 1.0f;
            }
        }
        out[0] = (count > 0.0f) ? (total / fmaxf(count, 1.0f)) : 0.0f;
    }
}

// ---------------- host launch ----------------------------------------------------
extern "C" void kernel_launch(void* const* d_in, const int* in_sizes, int n_in,
                              void* d_out, int out_size)
{
    const float* desc  = (const float*)d_in[0];
    const float* sf    = (const float*)d_in[1];
    const float* T     = (const float*)d_in[2];
    const float* W_rec = (const float*)d_in[3];
    const float* W_T   = (const float*)d_in[4];
    float* out = (float*)d_out;

    float *dn, *recon, *sim, *p, *rowsum, *colsum, *soft_row, *soft_col;
    int *rowidx, *colidx;
    cudaGetSymbolAddress((void**)&dn, g_dn);
    cudaGetSymbolAddress((void**)&recon, g_recon);
    cudaGetSymbolAddress((void**)&sim, g_sim);
    cudaGetSymbolAddress((void**)&p, g_p);
    cudaGetSymbolAddress((void**)&rowsum, g_rowsum);
    cudaGetSymbolAddress((void**)&colsum, g_colsum);
    cudaGetSymbolAddress((void**)&soft_row, g_soft_row);
    cudaGetSymbolAddress((void**)&soft_col, g_soft_col);
    cudaGetSymbolAddress((void**)&rowidx, g_rowidx);
    cudaGetSymbolAddress((void**)&colidx, g_colidx);

    // 1. normalize
    normalize_kernel<<<NN * VV, 256>>>(desc);

    // 2. rel @ W_T for all 12 ordered pairs
    relwt_kernel<<<12, 256>>>(T, W_T);

    // 3. recon[v] = dn_v @ W_rec  (batched over views via blockIdx.z)
    recon_gemm_kernel<<<dim3(CC / 64, NN / 128, VV), 256>>>(W_rec);

    auto OP = [](int i, int j) { return i * 3 + (j < i ? j : j - 1); };

    // 4. pairs
    for (int i = 0; i < VV; i++) {
        for (int j = i + 1; j < VV; j++) {
            // sim = dn_i @ dn_j^T
            gemm_nt_kernel<<<dim3(NN / 128, NN / 128), 256>>>(
                dn + i * CC, VV * CC, dn + j * CC, VV * CC, sim, NN, CC);

            // row direction (ordered pair (i,j))
            rowstats_kernel<<<NN, 256>>>();
            gemm_splitk_kernel<false><<<dim3(CC / 64, NN / 128, SPLITK), 256>>>(
                p, NN, sf + j * CC, VV * CC);
            splitk_reduce_kernel<<<NN * CC / 256, 256>>>(soft_row, rowsum);

            // column direction (ordered pair (j,i)) — uses sim^T implicitly
            colmax_part_kernel<<<dim3(NN / 256, 32), 256>>>();
            colmax_reduce_kernel<<<NN / 256, 256>>>();
            colexp_kernel<<<dim3(NN / 256, 32), 256>>>();
            colsum_reduce_kernel<<<NN / 256, 256>>>();
            gemm_splitk_kernel<true><<<dim3(CC / 64, NN / 128, SPLITK), 256>>>(
                p, NN, sf + i * CC, VV * CC);
            splitk_reduce_kernel<<<NN * CC / 256, 256>>>(soft_col, colsum);

            // losses for both ordered directions
            loss_kernel<<<32, 256>>>(rowidx, colidx, soft_row,
                                     recon + (size_t)i * NN * CC, OP(i, j));
            loss_kernel<<<32, 256>>>(colidx, rowidx, soft_col,
                                     recon + (size_t)j * NN * CC, OP(j, i));
        }
    }

    // 5. finalize
    finalize_kernel<<<1, 32>>>(out);
}

// round 3
// speedup vs baseline: 2.3488x; 1.4110x over previous
#include <cuda_runtime.h>
#include <cfloat>
#include <cstddef>

#define NN 4096
#define CC 256
#define VV 4
#define SPLITK 8
#define KCHUNK (NN / SPLITK)   // 512

// ---------------- scratch (static device globals; no cudaMalloc) ----------------
__device__ float g_dn[NN * VV * CC];
__device__ float g_recon[VV * NN * CC];
__device__ float g_relWT[12 * CC];
__device__ float g_sim[(size_t)NN * NN];
__device__ float g_p[(size_t)NN * NN];            // row-softmax numerators (selected rows)
__device__ float g_pT[(size_t)NN * NN];           // transposed col-softmax numerators (full)
__device__ float g_cpart[(size_t)SPLITK * NN * CC];

__device__ float g_rowmax_part[32 * NN];
__device__ int   g_rowidx_part[32 * NN];
__device__ float g_colmax_part[32 * NN];
__device__ int   g_colidx_part[32 * NN];
__device__ float g_rowmax[NN];
__device__ int   g_rowidx[NN];
__device__ float g_colmax[NN];
__device__ int   g_colidx[NN];
__device__ float g_rowsum[NN];
__device__ float g_colsum[NN];

__device__ int   g_rowlist[NN];
__device__ int   g_collist[NN];
__device__ int   g_segcnt[64];
__device__ int   g_segoff[64];
__device__ int   g_nsel[2];        // [0]=row count, [1]=col count

__device__ float g_soft_row[NN * CC];
__device__ float g_soft_col[NN * CC];
__device__ float g_sq_part[12 * 32];
__device__ int   g_cnt_part[12 * 32];

__constant__ int c_OPI[12] = {0,0,0,1,1,1,2,2,2,3,3,3};
__constant__ int c_OPJ[12] = {1,2,3,0,2,3,0,1,3,0,1,2};

// ---------------- fast exp (FMA-pipe polynomial) ---------------------------------
__device__ __forceinline__ float fast_exp(float x) {
    float y = x * 1.4426950408889634f;
    float n = rintf(y);
    float f = y - n;
    const float c1 = 0.6931471805599453f;
    const float c2 = 0.2402265069591007f;
    const float c3 = 0.0555041086648216f;
    const float c4 = 0.0096181291076285f;
    const float c5 = 0.0013333558146428f;
    const float c6 = 0.0001540353039338f;
    float r = c6;
    r = r * f + c5;
    r = r * f + c4;
    r = r * f + c3;
    r = r * f + c2;
    r = r * f + c1;
    r = r * f + 1.0f;
    int e = (int)n;
    return __int_as_float(__float_as_int(r) + (e << 23));
}

// ---------------- normalize ------------------------------------------------------
__global__ void __launch_bounds__(256) normalize_kernel(const float* __restrict__ desc) {
    int rv = blockIdx.x;
    int tid = threadIdx.x;
    __shared__ float ss[256];
    float x = desc[(size_t)rv * CC + tid];
    ss[tid] = x * x;
    __syncthreads();
    for (int off = 128; off > 0; off >>= 1) {
        if (tid < off) ss[tid] += ss[tid + off];
        __syncthreads();
    }
    float den = fmaxf(sqrtf(ss[0]), 1e-12f);
    g_dn[(size_t)rv * CC + tid] = x / den;
}

// ---------------- relWT ----------------------------------------------------------
__global__ void __launch_bounds__(256) relwt_kernel(const float* __restrict__ T,
                                                    const float* __restrict__ WT) {
    int op = blockIdx.x;
    int c = threadIdx.x;
    int i = c_OPI[op], j = c_OPJ[op];
    float s = 0.0f;
    #pragma unroll
    for (int k = 0; k < 16; k++) s += T[i * 16 + k] * WT[k * CC + c];
    #pragma unroll
    for (int k = 0; k < 16; k++) s += T[j * 16 + k] * WT[(16 + k) * CC + c];
    g_relWT[op * CC + c] = s;
}

// ---------------- recon GEMM (z-batched over views) ------------------------------
__global__ void __launch_bounds__(256) recon_gemm_kernel(const float* __restrict__ Wrec) {
    __shared__ float As[8][132];
    __shared__ float Bs[8][68];
    const int tid = threadIdx.x;
    const int v = blockIdx.z;
    const float* A = g_dn + v * CC;
    float* C = g_recon + (size_t)v * NN * CC;
    const int m0 = blockIdx.y * 128;
    const int n0 = blockIdx.x * 64;
    const int tx = (tid & 15) * 4;
    const int ty = (tid >> 4) * 8;
    const int lr = tid >> 1;
    const int lk = (tid & 1) * 4;
    const bool bload = tid < 128;
    const int bk = tid >> 4;
    const int bc = (tid & 15) * 4;

    float acc[8][4];
    #pragma unroll
    for (int i = 0; i < 8; i++)
        #pragma unroll
        for (int j = 0; j < 4; j++) acc[i][j] = 0.0f;

    for (int k0 = 0; k0 < CC; k0 += 8) {
        float4 a = *(const float4*)(A + (size_t)(m0 + lr) * (VV * CC) + k0 + lk);
        float4 b;
        if (bload) b = *(const float4*)(Wrec + (size_t)(k0 + bk) * CC + n0 + bc);
        __syncthreads();
        As[lk + 0][lr] = a.x; As[lk + 1][lr] = a.y; As[lk + 2][lr] = a.z; As[lk + 3][lr] = a.w;
        if (bload) *(float4*)&Bs[bk][bc] = b;
        __syncthreads();
        #pragma unroll
        for (int kk = 0; kk < 8; kk++) {
            float ar[8], br[4];
            *(float4*)(ar)     = *(const float4*)&As[kk][ty];
            *(float4*)(ar + 4) = *(const float4*)&As[kk][ty + 4];
            *(float4*)(br)     = *(const float4*)&Bs[kk][tx];
            #pragma unroll
            for (int i = 0; i < 8; i++)
                #pragma unroll
                for (int j = 0; j < 4; j++)
                    acc[i][j] += ar[i] * br[j];
        }
    }
    #pragma unroll
    for (int i = 0; i < 8; i++) {
        float* Cp = C + (size_t)(m0 + ty + i) * CC + n0 + tx;
        *(float4*)Cp = make_float4(acc[i][0], acc[i][1], acc[i][2], acc[i][3]);
    }
}

// ---------------- sim GEMM (NT) + fused row/col max partials, double-buffered ----
__global__ void __launch_bounds__(256) gemm_nt_stats_kernel(
    const float* __restrict__ A, int lda,
    const float* __restrict__ B, int ldb)
{
    __shared__ union {
        struct { float As[2][8][132]; float Bs[2][8][132]; } mm;
        struct { float cand[16][128]; int cidx[16][128]; } red;
    } sh;

    const int tid = threadIdx.x;
    const int lr = tid >> 1;
    const int lk = (tid & 1) * 4;
    const int row0 = blockIdx.y * 128;
    const int col0 = blockIdx.x * 128;
    const float* Ag = A + (size_t)(row0 + lr) * lda + lk;
    const float* Bg = B + (size_t)(col0 + lr) * ldb + lk;
    const int tx = (tid & 15) * 8;
    const int ty = (tid >> 4) * 8;
    float acc[8][8];
    #pragma unroll
    for (int i = 0; i < 8; i++)
        #pragma unroll
        for (int j = 0; j < 8; j++) acc[i][j] = 0.0f;

#define NT_COMPUTE(BUF)                                                        \
    _Pragma("unroll")                                                          \
    for (int kk = 0; kk < 8; kk++) {                                           \
        float ar[8], br[8];                                                    \
        *(float4*)(ar)     = *(const float4*)&sh.mm.As[BUF][kk][ty];           \
        *(float4*)(ar + 4) = *(const float4*)&sh.mm.As[BUF][kk][ty + 4];       \
        *(float4*)(br)     = *(const float4*)&sh.mm.Bs[BUF][kk][tx];           \
        *(float4*)(br + 4) = *(const float4*)&sh.mm.Bs[BUF][kk][tx + 4];       \
        _Pragma("unroll")                                                      \
        for (int i = 0; i < 8; i++)                                            \
            _Pragma("unroll")                                                  \
            for (int j = 0; j < 8; j++)                                        \
                acc[i][j] += ar[i] * br[j];                                    \
    }

    {
        float4 a = *(const float4*)(Ag);
        float4 b = *(const float4*)(Bg);
        sh.mm.As[0][lk + 0][lr] = a.x; sh.mm.As[0][lk + 1][lr] = a.y;
        sh.mm.As[0][lk + 2][lr] = a.z; sh.mm.As[0][lk + 3][lr] = a.w;
        sh.mm.Bs[0][lk + 0][lr] = b.x; sh.mm.Bs[0][lk + 1][lr] = b.y;
        sh.mm.Bs[0][lk + 2][lr] = b.z; sh.mm.Bs[0][lk + 3][lr] = b.w;
    }
    __syncthreads();
    int buf = 0;
    for (int kt = 1; kt < CC / 8; kt++) {
        float4 a = *(const float4*)(Ag + kt * 8);
        float4 b = *(const float4*)(Bg + kt * 8);
        NT_COMPUTE(buf);
        int nb = buf ^ 1;
        sh.mm.As[nb][lk + 0][lr] = a.x; sh.mm.As[nb][lk + 1][lr] = a.y;
        sh.mm.As[nb][lk + 2][lr] = a.z; sh.mm.As[nb][lk + 3][lr] = a.w;
        sh.mm.Bs[nb][lk + 0][lr] = b.x; sh.mm.Bs[nb][lk + 1][lr] = b.y;
        sh.mm.Bs[nb][lk + 2][lr] = b.z; sh.mm.Bs[nb][lk + 3][lr] = b.w;
        __syncthreads();
        buf = nb;
    }
    NT_COMPUTE(buf);
#undef NT_COMPUTE

    // write sim tile
    #pragma unroll
    for (int i = 0; i < 8; i++) {
        float* Cp = g_sim + (size_t)(row0 + ty + i) * NN + col0 + tx;
        *(float4*)(Cp)     = make_float4(acc[i][0], acc[i][1], acc[i][2], acc[i][3]);
        *(float4*)(Cp + 4) = make_float4(acc[i][4], acc[i][5], acc[i][6], acc[i][7]);
    }

    // ---- fused row-max partials (per col-tile) ----
    __syncthreads();   // done with mm smem
    const int txg = tid & 15;          // col group
    const int tyg = tid >> 4;          // row group
    #pragma unroll
    for (int i = 0; i < 8; i++) {
        float m = acc[i][0]; int jx = 0;
        #pragma unroll
        for (int j = 1; j < 8; j++)
            if (acc[i][j] > m) { m = acc[i][j]; jx = j; }
        sh.red.cand[txg][ty + i] = m;
        sh.red.cidx[txg][ty + i] = tx + jx;
    }
    __syncthreads();
    if (tid < 128) {
        float best = sh.red.cand[0][tid];
        int bidx = sh.red.cidx[0][tid];
        #pragma unroll
        for (int s = 1; s < 16; s++) {
            float v = sh.red.cand[s][tid];
            if (v > best) { best = v; bidx = sh.red.cidx[s][tid]; }
        }
        g_rowmax_part[blockIdx.x * NN + row0 + tid] = best;
        g_rowidx_part[blockIdx.x * NN + row0 + tid] = col0 + bidx;
    }
    __syncthreads();
    // ---- fused col-max partials (per row-tile) ----
    #pragma unroll
    for (int j = 0; j < 8; j++) {
        float m = acc[0][j]; int ii = 0;
        #pragma unroll
        for (int i = 1; i < 8; i++)
            if (acc[i][j] > m) { m = acc[i][j]; ii = i; }
        sh.red.cand[tyg][tx + j] = m;
        sh.red.cidx[tyg][tx + j] = ty + ii;
    }
    __syncthreads();
    if (tid < 128) {
        float best = sh.red.cand[0][tid];
        int bidx = sh.red.cidx[0][tid];
        #pragma unroll
        for (int s = 1; s < 16; s++) {
            float v = sh.red.cand[s][tid];
            if (v > best) { best = v; bidx = sh.red.cidx[s][tid]; }
        }
        g_colmax_part[blockIdx.y * NN + col0 + tid] = best;
        g_colidx_part[blockIdx.y * NN + col0 + tid] = row0 + bidx;
    }
}

// ---------------- final max reduce (row + col), ascending tiles -------------------
__global__ void __launch_bounds__(256) maxreduce_kernel() {
    int n = blockIdx.x * 256 + threadIdx.x;
    float bm = g_rowmax_part[n]; int bi = g_rowidx_part[n];
    for (int s = 1; s < 32; s++) {
        float v = g_rowmax_part[s * NN + n];
        if (v > bm) { bm = v; bi = g_rowidx_part[s * NN + n]; }
    }
    g_rowmax[n] = bm; g_rowidx[n] = bi;
    bm = g_colmax_part[n]; bi = g_colidx_part[n];
    for (int s = 1; s < 32; s++) {
        float v = g_colmax_part[s * NN + n];
        if (v > bm) { bm = v; bi = g_colidx_part[s * NN + n]; }
    }
    g_colmax[n] = bm; g_colidx[n] = bi;
}

// ---------------- mutual compaction: count / scan / fill -------------------------
__device__ __forceinline__ int mutual_flag(int b, int t) {
    if (b < 32) { int n = b * 128 + t; return g_colidx[g_rowidx[n]] == n; }
    else        { int m = (b - 32) * 128 + t; return g_rowidx[g_colidx[m]] == m; }
}

__global__ void __launch_bounds__(128) countseg_kernel() {
    int b = blockIdx.x, t = threadIdx.x;
    __shared__ int sc[128];
    sc[t] = mutual_flag(b, t);
    __syncthreads();
    for (int off = 64; off > 0; off >>= 1) {
        if (t < off) sc[t] += sc[t + off];
        __syncthreads();
    }
    if (t == 0) g_segcnt[b] = sc[0];
}

__global__ void scanseg_kernel() {
    if (threadIdx.x == 0) {
        int off = 0;
        for (int s = 0; s < 32; s++) { g_segoff[s] = off; off += g_segcnt[s]; }
        g_nsel[0] = off;
        off = 0;
        for (int s = 32; s < 64; s++) { g_segoff[s] = off; off += g_segcnt[s]; }
        g_nsel[1] = off;
    }
}

__global__ void __launch_bounds__(128) fillseg_kernel() {
    int b = blockIdx.x, t = threadIdx.x;
    int flag = mutual_flag(b, t);
    __shared__ int sc[128];
    sc[t] = flag;
    __syncthreads();
    for (int off = 1; off < 128; off <<= 1) {
        int v = (t >= off) ? sc[t - off] : 0;
        __syncthreads();
        sc[t] += v;
        __syncthreads();
    }
    if (flag) {
        int rank = sc[t] - 1;
        int idx = (b & 31) * 128 + t;
        if (b < 32) g_rowlist[g_segoff[b] + rank] = idx;
        else        g_collist[g_segoff[b] + rank] = idx;
    }
}

// ---------------- selected row exp + sum ------------------------------------------
__global__ void __launch_bounds__(256) rowexp_sel_kernel() {
    int b = blockIdx.x;
    if (b >= g_nsel[0]) return;
    int row = g_rowlist[b];
    int tid = threadIdx.x;
    const float* srow = g_sim + (size_t)row * NN;
    float* prow = g_p + (size_t)row * NN;
    float rmax = g_rowmax[row];
    float lsum = 0.0f;
    #pragma unroll
    for (int s = 0; s < 16; s++) {
        int idx = tid + 256 * s;
        float e = fast_exp(srow[idx] - rmax);
        prow[idx] = e;
        lsum += e;
    }
    __shared__ float sv[256];
    sv[tid] = lsum;
    __syncthreads();
    for (int off = 128; off > 0; off >>= 1) {
        if (tid < off) sv[tid] += sv[tid + off];
        __syncthreads();
    }
    if (tid == 0) g_rowsum[row] = sv[0];
}

// ---------------- transposed col exp: pT[m][k] = exp(sim[k][m] - colmax[m]) ------
__global__ void __launch_bounds__(256) transpose_exp_kernel() {
    __shared__ float tile[32][33];
    int m0 = blockIdx.x * 32;
    int k0 = blockIdx.y * 32;
    int tx = threadIdx.x & 31;
    int ty = threadIdx.x >> 5;   // 0..7
    #pragma unroll
    for (int q = 0; q < 4; q++) {
        int r = ty * 4 + q;
        tile[r][tx] = g_sim[(size_t)(k0 + r) * NN + m0 + tx];
    }
    __syncthreads();
    #pragma unroll
    for (int q = 0; q < 4; q++) {
        int r = ty * 4 + q;
        float cm = g_colmax[m0 + r];
        g_pT[(size_t)(m0 + r) * NN + k0 + tx] = fast_exp(tile[tx][r] - cm);
    }
}

// ---------------- selected col sums (rows of pT) ----------------------------------
__global__ void __launch_bounds__(256) colsum_sel_kernel() {
    int b = blockIdx.x;
    if (b >= g_nsel[1]) return;
    int m = g_collist[b];
    int tid = threadIdx.x;
    const float* prow = g_pT + (size_t)m * NN;
    float lsum = 0.0f;
    #pragma unroll
    for (int s = 0; s < 16; s++) lsum += prow[tid + 256 * s];
    __shared__ float sv[256];
    sv[tid] = lsum;
    __syncthreads();
    for (int off = 128; off > 0; off >>= 1) {
        if (tid < off) sv[tid] += sv[tid + off];
        __syncthreads();
    }
    if (tid == 0) g_colsum[m] = sv[0];
}

// ---------------- selected weighted GEMM: Cpart[z][slot] = P[list[slot]] @ B ------
// 128x128 tile, 8x8 microtile, split-K, double-buffered. B is NN x CC (ldb).
__global__ void __launch_bounds__(256) gemm_sel_kernel(
    const float* __restrict__ P,
    const int* __restrict__ list,
    const int* __restrict__ cntp,
    const float* __restrict__ B, int ldb)
{
    const int m0 = blockIdx.y * 128;
    if (m0 >= *cntp) return;
    __shared__ float As[2][8][132];
    __shared__ float Bs[2][8][132];
    const int tid = threadIdx.x;
    const int n0 = blockIdx.x * 128;
    const int kb = blockIdx.z * KCHUNK;
    const int lr = tid >> 1;
    const int lk = (tid & 1) * 4;
    const int bk = tid >> 5;
    const int bc = (tid & 31) * 4;
    const int tx = (tid & 15) * 8;
    const int ty = (tid >> 4) * 8;

    const int arow = list[m0 + lr];
    const float* Ag = P + (size_t)arow * NN + lk;
    const float* Bg = B + n0 + bc;

    float acc[8][8];
    #pragma unroll
    for (int i = 0; i < 8; i++)
        #pragma unroll
        for (int j = 0; j < 8; j++) acc[i][j] = 0.0f;

#define SEL_COMPUTE(BUF)                                                       \
    _Pragma("unroll")                                                          \
    for (int kk = 0; kk < 8; kk++) {                                           \
        float ar[8], br[8];                                                    \
        *(float4*)(ar)     = *(const float4*)&As[BUF][kk][ty];                 \
        *(float4*)(ar + 4) = *(const float4*)&As[BUF][kk][ty + 4];             \
        *(float4*)(br)     = *(const float4*)&Bs[BUF][kk][tx];                 \
        *(float4*)(br + 4) = *(const float4*)&Bs[BUF][kk][tx + 4];             \
        _Pragma("unroll")                                                      \
        for (int i = 0; i < 8; i++)                                            \
            _Pragma("unroll")                                                  \
            for (int j = 0; j < 8; j++)                                        \
                acc[i][j] += ar[i] * br[j];                                    \
    }

    {
        float4 a = *(const float4*)(Ag + kb);
        float4 b = *(const float4*)(Bg + (size_t)(kb + bk) * ldb);
        As[0][lk + 0][lr] = a.x; As[0][lk + 1][lr] = a.y;
        As[0][lk + 2][lr] = a.z; As[0][lk + 3][lr] = a.w;
        *(float4*)&Bs[0][bk][bc] = b;
    }
    __syncthreads();
    int buf = 0;
    for (int kt = 1; kt < KCHUNK / 8; kt++) {
        int k0 = kb + kt * 8;
        float4 a = *(const float4*)(Ag + k0);
        float4 b = *(const float4*)(Bg + (size_t)(k0 + bk) * ldb);
        SEL_COMPUTE(buf);
        int nb = buf ^ 1;
        As[nb][lk + 0][lr] = a.x; As[nb][lk + 1][lr] = a.y;
        As[nb][lk + 2][lr] = a.z; As[nb][lk + 3][lr] = a.w;
        *(float4*)&Bs[nb][bk][bc] = b;
        __syncthreads();
        buf = nb;
    }
    SEL_COMPUTE(buf);
#undef SEL_COMPUTE

    float* Cp0 = g_cpart + (size_t)blockIdx.z * NN * CC;
    #pragma unroll
    for (int i = 0; i < 8; i++) {
        float* Cp = Cp0 + (size_t)(m0 + ty + i) * CC + n0 + tx;
        *(float4*)(Cp)     = make_float4(acc[i][0], acc[i][1], acc[i][2], acc[i][3]);
        *(float4*)(Cp + 4) = make_float4(acc[i][4], acc[i][5], acc[i][6], acc[i][7]);
    }
}

// ---------------- split-K reduce for selected slots, scatter + normalize ----------
__global__ void __launch_bounds__(256) reduce_sel_kernel(
    float* __restrict__ soft, const float* __restrict__ den,
    const int* __restrict__ list, const int* __restrict__ cntp)
{
    int slot = blockIdx.x;
    if (slot >= *cntp) return;
    int row = list[slot];
    int c = threadIdx.x;
    float s = 0.0f;
    #pragma unroll
    for (int z = 0; z < SPLITK; z++)
        s += g_cpart[(size_t)z * NN * CC + (size_t)slot * CC + c];
    soft[(size_t)row * CC + c] = s / den[row];
}

// ---------------- per-ordered-pair loss partials ----------------------------------
__global__ void __launch_bounds__(256) loss_kernel(
    const int* __restrict__ idxA, const int* __restrict__ idxB,
    const float* __restrict__ soft, const float* __restrict__ recon, int op)
{
    int tid = threadIdx.x;
    int b = blockIdx.x;
    float relc = g_relWT[op * CC + tid];
    float lsum = 0.0f;
    int lcnt = 0;
    for (int r = 0; r < 128; r++) {
        int row = b * 128 + r;
        int a = idxA[row];
        if (idxB[a] == row) {
            float d = recon[(size_t)row * CC + tid] + relc - soft[(size_t)row * CC + tid];
            lsum += d * d;
            if (tid == 0) lcnt++;
        }
    }
    __shared__ float ss[256];
    ss[tid] = lsum;
    __syncthreads();
    for (int off = 128; off > 0; off >>= 1) {
        if (tid < off) ss[tid] += ss[tid + off];
        __syncthreads();
    }
    if (tid == 0) {
        g_sq_part[op * 32 + b] = ss[0];
        g_cnt_part[op * 32 + b] = lcnt;
    }
}

__global__ void finalize_kernel(float* __restrict__ out) {
    if (threadIdx.x == 0) {
        float total = 0.0f, count = 0.0f;
        for (int op = 0; op < 12; op++) {
            float sq = 0.0f;
            int cnt = 0;
            for (int b = 0; b < 32; b++) {
                sq += g_sq_part[op * 32 + b];
                cnt += g_cnt_part[op * 32 + b];
            }
            if (cnt > 0) {
                total += sq / fmaxf((float)cnt * (float)CC, 1.0f);
                count += 1.0f;
            }
        }
        out[0] = (count > 0.0f) ? (total / fmaxf(count, 1.0f)) : 0.0f;
    }
}

// ---------------- host launch ------------------------------------------------------
extern "C" void kernel_launch(void* const* d_in, const int* in_sizes, int n_in,
                              void* d_out, int out_size)
{
    const float* desc  = (const float*)d_in[0];
    const float* sf    = (const float*)d_in[1];
    const float* T     = (const float*)d_in[2];
    const float* W_rec = (const float*)d_in[3];
    const float* W_T   = (const float*)d_in[4];
    float* out = (float*)d_out;

    float *dn, *p, *pT, *recon, *rowsum, *colsum, *soft_row, *soft_col;
    int *rowidx, *colidx, *rowlist, *collist, *nsel;
    cudaGetSymbolAddress((void**)&dn, g_dn);
    cudaGetSymbolAddress((void**)&p, g_p);
    cudaGetSymbolAddress((void**)&pT, g_pT);
    cudaGetSymbolAddress((void**)&recon, g_recon);
    cudaGetSymbolAddress((void**)&rowsum, g_rowsum);
    cudaGetSymbolAddress((void**)&colsum, g_colsum);
    cudaGetSymbolAddress((void**)&soft_row, g_soft_row);
    cudaGetSymbolAddress((void**)&soft_col, g_soft_col);
    cudaGetSymbolAddress((void**)&rowidx, g_rowidx);
    cudaGetSymbolAddress((void**)&colidx, g_colidx);
    cudaGetSymbolAddress((void**)&rowlist, g_rowlist);
    cudaGetSymbolAddress((void**)&collist, g_collist);
    cudaGetSymbolAddress((void**)&nsel, g_nsel);

    normalize_kernel<<<NN * VV, 256>>>(desc);
    relwt_kernel<<<12, 256>>>(T, W_T);
    recon_gemm_kernel<<<dim3(CC / 64, NN / 128, VV), 256>>>(W_rec);

    auto OP = [](int i, int j) { return i * 3 + (j < i ? j : j - 1); };

    for (int i = 0; i < VV; i++) {
        for (int j = i + 1; j < VV; j++) {
            // sim + fused max partials
            gemm_nt_stats_kernel<<<dim3(NN / 128, NN / 128), 256>>>(
                dn + i * CC, VV * CC, dn + j * CC, VV * CC);
            maxreduce_kernel<<<NN / 256, 256>>>();

            // deterministic mutual compaction (both directions)
            countseg_kernel<<<64, 128>>>();
            scanseg_kernel<<<1, 32>>>();
            cudaMemsetAsync(rowlist, 0, NN * sizeof(int));
            cudaMemsetAsync(collist, 0, NN * sizeof(int));
            fillseg_kernel<<<64, 128>>>();

            // row direction: exp selected rows, weighted GEMM, scatter
            rowexp_sel_kernel<<<NN, 256>>>();
            gemm_sel_kernel<<<dim3(CC / 128, NN / 128, SPLITK), 256>>>(
                p, rowlist, nsel + 0, sf + j * CC, VV * CC);
            reduce_sel_kernel<<<NN, 256>>>(soft_row, rowsum, rowlist, nsel + 0);

            // col direction: transposed exp (full), selected sums, weighted GEMM
            transpose_exp_kernel<<<dim3(NN / 32, NN / 32), 256>>>();
            colsum_sel_kernel<<<NN, 256>>>();
            gemm_sel_kernel<<<dim3(CC / 128, NN / 128, SPLITK), 256>>>(
                pT, collist, nsel + 1, sf + i * CC, VV * CC);
            reduce_sel_kernel<<<NN, 256>>>(soft_col, colsum, collist, nsel + 1);

            // losses
            loss_kernel<<<32, 256>>>(rowidx, colidx, soft_row,
                                     recon + (size_t)i * NN * CC, OP(i, j));
            loss_kernel<<<32, 256>>>(colidx, rowidx, soft_col,
                                     recon + (size_t)j * NN * CC, OP(j, i));
        }
    }

    finalize_kernel<<<1, 32>>>(out);
}